// round 15
// baseline (speedup 1.0000x reference)
#include <cuda_runtime.h>
#include <math.h>
#include <stdint.h>

// Fixed problem shapes
#define HOP 256
#define NFFT 2048
#define NPITCH 256
#define BATCH 16
#define NSAMP 480000
#define TFRAMES 1876
#define KLA 102           // LA bins 0..101
#define LPAD 168          // zero-pad in front of LS (max shift 165)

struct Params {
    int   closest[NPITCH];
    int   shift[8];
    float wgt[8];
};

#define CR 0.7071067811865476f

__device__ __forceinline__ void bfly4(
    float& r0, float& i0, float& r1, float& i1,
    float& r2, float& i2, float& r3, float& i3,
    float c1, float s1, float c2, float s2, float c3, float s3)
{
    float t0r = r0 + r2, t0i = i0 + i2;
    float t1r = r1 + r3, t1i = i1 + i3;
    float t2r = r0 - r2, t2i = i0 - i2;
    float t3r = r1 - r3, t3i = i1 - i3;
    float y0r = t0r + t1r, y0i = t0i + t1i;
    float y2r = t0r - t1r, y2i = t0i - t1i;
    float y1r = t2r + t3i, y1i = t2i - t3r;
    float y3r = t2r - t3i, y3i = t2i + t3r;
    r0 = y0r;                 i0 = y0i;
    r1 = y1r * c1 - y1i * s1; i1 = y1r * s1 + y1i * c1;
    r2 = y2r * c2 - y2i * s2; i2 = y2r * s2 + y2i * c2;
    r3 = y3r * c3 - y3i * s3; i3 = y3r * s3 + y3i * c3;
}

// In-register 32-pt DIF FFT (radix 4,4,2). Output position p holds bin
// k = (p>>3) + 4*((p>>1)&3) + 16*(p&1). All twiddles are literals.
__device__ __forceinline__ void fft32(float* zr, float* zi)
{
    constexpr float T32C[8] = { 1.0f, 0.98078528040323044913f, 0.92387953251128675613f,
        0.83146961230254523708f, 0.70710678118654752440f, 0.55557023301960222474f,
        0.38268343236508977173f, 0.19509032201612826785f };
    constexpr float T32S[8] = { 0.0f, -0.19509032201612826785f, -0.38268343236508977173f,
        -0.55557023301960222474f, -0.70710678118654752440f, -0.83146961230254523708f,
        -0.92387953251128675613f, -0.98078528040323044913f };
    constexpr float T16C[8] = { 1.0f, 0.92387953251128675613f, 0.70710678118654752440f,
        0.38268343236508977173f, 0.0f, -0.38268343236508977173f,
        -0.70710678118654752440f, -0.92387953251128675613f };
    constexpr float T16S[8] = { 0.0f, -0.38268343236508977173f, -0.70710678118654752440f,
        -0.92387953251128675613f, -1.0f, -0.92387953251128675613f,
        -0.70710678118654752440f, -0.38268343236508977173f };
    constexpr float T96C[8] = { 1.0f, 0.83146961230254523708f, 0.38268343236508977173f,
        -0.19509032201612826785f, -0.70710678118654752440f, -0.98078528040323044913f,
        -0.92387953251128675613f, -0.55557023301960222474f };
    constexpr float T96S[8] = { 0.0f, -0.55557023301960222474f, -0.92387953251128675613f,
        -0.98078528040323044913f, -0.70710678118654752440f, -0.19509032201612826785f,
        0.38268343236508977173f, 0.83146961230254523708f };

    #pragma unroll
    for (int q = 0; q < 8; ++q)
        bfly4(zr[q], zi[q], zr[q + 8], zi[q + 8], zr[q + 16], zi[q + 16],
              zr[q + 24], zi[q + 24],
              T32C[q], T32S[q], T16C[q], T16S[q], T96C[q], T96S[q]);

    #pragma unroll
    for (int g = 0; g < 4; ++g) {
        const int bb = 8 * g;
        bfly4(zr[bb], zi[bb], zr[bb + 2], zi[bb + 2], zr[bb + 4], zi[bb + 4],
              zr[bb + 6], zi[bb + 6], 1.f, 0.f, 1.f, 0.f, 1.f, 0.f);
        bfly4(zr[bb + 1], zi[bb + 1], zr[bb + 3], zi[bb + 3], zr[bb + 5], zi[bb + 5],
              zr[bb + 7], zi[bb + 7], CR, -CR, 0.f, -1.f, -CR, -CR);
    }

    #pragma unroll
    for (int m = 0; m < 16; ++m) {
        float ar = zr[2 * m], ai = zi[2 * m];
        float br = zr[2 * m + 1], bi = zi[2 * m + 1];
        zr[2 * m] = ar + br;     zi[2 * m] = ai + bi;
        zr[2 * m + 1] = ar - br; zi[2 * m + 1] = ai - bi;
    }
}

__global__ __launch_bounds__(32, 28)
void pitch_kernel(const float* __restrict__ wav, float* __restrict__ out, Params p)
{
    // TR: XOR-swizzled 32x32 float2 transpose buffer (exactly 1024 f2 = 8192 B).
    // After TR is consumed, SPX/LA/CS1/LSB alias the same storage.
    __shared__ __align__(16) float SH[2048];
    float2* TR  = reinterpret_cast<float2*>(SH);
    float2* SPX = reinterpret_cast<float2*>(SH);            // bins 0..102 (f2[0..103))
    float*  LA  = SH + 208;                                 // [208,312)
    float*  CS1 = SH + 312;                                 // [312,416)
    float*  LSB = SH + 416;                                 // [416,840)

    const int lane = threadIdx.x;     // 0..31
    const int t    = blockIdx.x;
    const int b    = blockIdx.y;
    const float* w = wav + (size_t)b * NSAMP;
    const int base = t * HOP - (NFFT / 2);
    const unsigned FM = 0xffffffffu;

    // ---- load: thread n2=lane holds packed z[32*n1 + lane], n1 = 0..31 ----
    float zr[32], zi[32];
    if (base >= 0 && base + NFFT <= NSAMP) {
        const float2* src = reinterpret_cast<const float2*>(w + base);
        #pragma unroll
        for (int n1 = 0; n1 < 32; ++n1) {
            float2 v = src[32 * n1 + lane];
            zr[n1] = v.x; zi[n1] = v.y;
        }
    } else {
        #pragma unroll
        for (int n1 = 0; n1 < 32; ++n1) {
            int m  = 32 * n1 + lane;
            int p0 = base + 2 * m, p1 = p0 + 1;
            p0 = p0 < 0 ? -p0 : (p0 >= NSAMP ? 2 * NSAMP - 2 - p0 : p0);
            p1 = p1 < 0 ? -p1 : (p1 >= NSAMP ? 2 * NSAMP - 2 - p1 : p1);
            zr[n1] = w[p0]; zi[n1] = w[p1];
        }
    }

    // ---- step 1: full 32-pt FFT over n1 ----
    fft32(zr, zi);

    // ---- twiddle W1024^{n2*k1} via sequential recurrence, transpose-store ----
    {
        float bc, bs; __sincosf((float)lane * (-6.283185307179586f / 1024.0f), &bs, &bc);
        float wc = 1.0f, ws = 0.0f;            // W1024^{lane*k1}, advanced per k1
        #pragma unroll
        for (int k1 = 0; k1 < 32; ++k1) {
            const int pp = 8 * (k1 & 3) + 2 * ((k1 >> 2) & 3) + (k1 >> 4);
            TR[32 * k1 + (lane ^ k1)] =
                make_float2(zr[pp] * wc - zi[pp] * ws,
                            zr[pp] * ws + zi[pp] * wc);
            float nc = wc * bc - ws * bs;
            ws = wc * bs + ws * bc;
            wc = nc;
        }
    }
    __syncwarp();

    // ---- step 2: pruned streaming 32-pt DFT over n2 (thread = row k1 = lane).
    //      Needed k2 in {0,1,2,3,28,29,30,31}: Y[k2] = sum_j W32^{j*k2} V_j[k2&3],
    //      V_j[r] = 4-pt DFT over m of row[j+8m]. All twiddles literal. ----
    float accR[8] = {0,0,0,0,0,0,0,0}, accI[8] = {0,0,0,0,0,0,0,0};
    {
        constexpr float C32[32] = {
            1.0f, 0.98078528040323044913f, 0.92387953251128675613f, 0.83146961230254523708f,
            0.70710678118654752440f, 0.55557023301960222474f, 0.38268343236508977173f,
            0.19509032201612826785f, 0.0f, -0.19509032201612826785f, -0.38268343236508977173f,
            -0.55557023301960222474f, -0.70710678118654752440f, -0.83146961230254523708f,
            -0.92387953251128675613f, -0.98078528040323044913f, -1.0f,
            -0.98078528040323044913f, -0.92387953251128675613f, -0.83146961230254523708f,
            -0.70710678118654752440f, -0.55557023301960222474f, -0.38268343236508977173f,
            -0.19509032201612826785f, 0.0f, 0.19509032201612826785f, 0.38268343236508977173f,
            0.55557023301960222474f, 0.70710678118654752440f, 0.83146961230254523708f,
            0.92387953251128675613f, 0.98078528040323044913f };
        constexpr float S32[32] = {
            0.0f, -0.19509032201612826785f, -0.38268343236508977173f, -0.55557023301960222474f,
            -0.70710678118654752440f, -0.83146961230254523708f, -0.92387953251128675613f,
            -0.98078528040323044913f, -1.0f, -0.98078528040323044913f,
            -0.92387953251128675613f, -0.83146961230254523708f, -0.70710678118654752440f,
            -0.55557023301960222474f, -0.38268343236508977173f, -0.19509032201612826785f,
            0.0f, 0.19509032201612826785f, 0.38268343236508977173f, 0.55557023301960222474f,
            0.70710678118654752440f, 0.83146961230254523708f, 0.92387953251128675613f,
            0.98078528040323044913f, 1.0f, 0.98078528040323044913f, 0.92387953251128675613f,
            0.83146961230254523708f, 0.70710678118654752440f, 0.55557023301960222474f,
            0.38268343236508977173f, 0.19509032201612826785f };
        constexpr int K2V[8] = {0, 1, 2, 3, 28, 29, 30, 31};

        #pragma unroll
        for (int j = 0; j < 8; ++j) {
            float2 a0 = TR[32 * lane + ((j     ) ^ lane)];
            float2 a1 = TR[32 * lane + ((j +  8) ^ lane)];
            float2 a2 = TR[32 * lane + ((j + 16) ^ lane)];
            float2 a3 = TR[32 * lane + ((j + 24) ^ lane)];
            float t0r = a0.x + a2.x, t0i = a0.y + a2.y;
            float t1r = a1.x + a3.x, t1i = a1.y + a3.y;
            float t2r = a0.x - a2.x, t2i = a0.y - a2.y;
            float t3r = a1.x - a3.x, t3i = a1.y - a3.y;
            float VR[4], VI[4];
            VR[0] = t0r + t1r;  VI[0] = t0i + t1i;
            VR[2] = t0r - t1r;  VI[2] = t0i - t1i;
            VR[1] = t2r + t3i;  VI[1] = t2i - t3r;     // t2 - i*t3
            VR[3] = t2r - t3i;  VI[3] = t2i + t3r;     // t2 + i*t3
            #pragma unroll
            for (int q = 0; q < 8; ++q) {
                const int k2 = K2V[q];
                const int r  = k2 & 3;
                const int tt = (k2 * j) & 31;
                accR[q] = fmaf(C32[tt], VR[r], fmaf(-S32[tt], VI[r], accR[q]));
                accI[q] = fmaf(C32[tt], VI[r], fmaf( S32[tt], VR[r], accI[q]));
            }
        }
    }
    __syncwarp();   // all TR reads done before SPX (aliased) writes

    // ---- rfft unpack in registers via shuffles -> SPX[0..102] ----
    // Thread lane holds bins lane+32q (q=0..3) and lane+896+32(q-4) (q=4..7).
    // Partner of bin k=lane+32q is bin 1024-k = (32-lane)&31 thread, acc[7-q]
    // (lane 0, q>=1: its own acc[8-q]; lane 0, q==0: conj self).
    {
        const int src = (32 - lane) & 31;
        #pragma unroll
        for (int q = 0; q < 4; ++q) {
            float br = __shfl_sync(FM, accR[7 - q], src);
            float bi = __shfl_sync(FM, accI[7 - q], src);
            if (lane == 0 && q > 0) { br = accR[8 - q]; bi = accI[8 - q]; }
            float Ar = accR[q], Ai = accI[q];
            float Br, Bi;
            if (q == 0 && lane == 0) { Br = Ar; Bi = Ai; }
            else                     { Br = br; Bi = bi; }
            int k = lane + 32 * q;
            float zer =  0.5f * (Ar + Br);
            float zei =  0.5f * (Ai - Bi);
            float zor =  0.5f * (Ai + Bi);
            float zoi = -0.5f * (Ar - Br);
            float sn, cs;
            __sincosf((float)k * (-3.141592653589793f / 1024.0f), &sn, &cs);
            if (q < 3 || lane <= 6)
                SPX[k] = make_float2(zer + cs * zor - sn * zoi,
                                     zei + cs * zoi + sn * zor);
        }
    }
    __syncwarp();

    // ---- window as spectral conv + log magnitude -> LA[0..101] ----
    #pragma unroll
    for (int it = 0; it < 4; ++it) {
        int k = lane + 32 * it;
        if (it < 3 || lane <= 5) {      // k < 102
            float2 Xc = SPX[k];
            float2 Xp = SPX[k + 1];
            float2 Xm = (k == 0) ? make_float2(SPX[1].x, -SPX[1].y) : SPX[k - 1];
            float xr = 0.5f * Xc.x - 0.25f * (Xm.x + Xp.x);
            float xi = 0.5f * Xc.y - 0.25f * (Xm.y + Xp.y);
            LA[k] = __logf(sqrtf(xr * xr + xi * xi) + 1e-8f);
        }
    }
    if (lane < 2) LA[KLA + lane] = 0.f;
    #pragma unroll
    for (int i = lane; i < LPAD / 4; i += 32)
        reinterpret_cast<float4*>(LSB)[i] = make_float4(0.f, 0.f, 0.f, 0.f);
    __syncwarp();

    // ---- single-pass warp scan: CS1 inclusive prefix of LA ----
    {
        float v0 = 0.f, v1 = 0.f, v2 = 0.f, v3 = 0.f;
        if (lane < 26) {
            float4 q = reinterpret_cast<const float4*>(LA)[lane];
            v0 = q.x; v1 = q.y; v2 = q.z; v3 = q.w;
        }
        float p1 = v0 + v1, p2 = p1 + v2, p3 = p2 + v3;
        float s = p3;
        #pragma unroll
        for (int o = 1; o < 32; o <<= 1) {
            float u = __shfl_up_sync(FM, s, o);
            if (lane >= o) s += u;
        }
        float excl = s - p3;
        if (lane < 26)
            reinterpret_cast<float4*>(CS1)[lane] =
                make_float4(excl + v0, excl + p1, excl + p2, excl + p3);
    }
    __syncwarp();

    // ---- fine structure: 8 pitch bins per thread (two float4 groups) ----
    float lsv[2][4];
    #pragma unroll
    for (int g = 0; g < 2; ++g) {
        int vt = lane + 32 * g;
        int4 c4 = reinterpret_cast<const int4*>(p.closest)[vt];
        int cis[4] = {c4.x, c4.y, c4.z, c4.w};
        float LA0 = LA[0];
        #pragma unroll
        for (int j = 0; j < 4; ++j) {
            int ci = cis[j];                  // 3..85
            int lo = ci - 15, hi = ci + 16;   // hi <= 101
            float sum = (lo <= 0) ? fmaf((float)(-lo), LA0, CS1[hi])
                                  : CS1[hi] - CS1[lo - 1];
            lsv[g][j] = __expf(LA[ci] - sum * 0.03125f);
        }
        *reinterpret_cast<float4*>(&LSB[LPAD + 4 * vt]) =
            make_float4(lsv[g][0], lsv[g][1], lsv[g][2], lsv[g][3]);
    }
    __syncwarp();

    // ---- subharmonic summation (zero-padded, guard-free) ----
    float acc[2][4];
    #pragma unroll
    for (int g = 0; g < 2; ++g)
        #pragma unroll
        for (int j = 0; j < 4; ++j) acc[g][j] = lsv[g][j];

    #pragma unroll
    for (int n = 1; n < 8; ++n) {
        int   sh = p.shift[n];
        float wn = p.wgt[n];
        #pragma unroll
        for (int g = 0; g < 2; ++g) {
            int bi = LPAD + 4 * (lane + 32 * g) - sh;     // >= 3 always
            if ((sh & 3) == 0) {
                float4 q = *reinterpret_cast<const float4*>(&LSB[bi]);
                acc[g][0] = fmaf(wn, q.x, acc[g][0]);
                acc[g][1] = fmaf(wn, q.y, acc[g][1]);
                acc[g][2] = fmaf(wn, q.z, acc[g][2]);
                acc[g][3] = fmaf(wn, q.w, acc[g][3]);
            } else if ((sh & 1) == 0) {
                float2 qa = *reinterpret_cast<const float2*>(&LSB[bi]);
                float2 qb = *reinterpret_cast<const float2*>(&LSB[bi + 2]);
                acc[g][0] = fmaf(wn, qa.x, acc[g][0]);
                acc[g][1] = fmaf(wn, qa.y, acc[g][1]);
                acc[g][2] = fmaf(wn, qb.x, acc[g][2]);
                acc[g][3] = fmaf(wn, qb.y, acc[g][3]);
            } else {
                #pragma unroll
                for (int j = 0; j < 4; ++j)
                    acc[g][j] = fmaf(wn, LSB[bi + j], acc[g][j]);
            }
        }
    }

    // ---- per-frame max (pure warp shuffle), normalize, store ----
    float mloc = -3.4e38f;
    #pragma unroll
    for (int g = 0; g < 2; ++g)
        #pragma unroll
        for (int j = 0; j < 4; ++j) mloc = fmaxf(mloc, acc[g][j]);
    #pragma unroll
    for (int o = 16; o; o >>= 1)
        mloc = fmaxf(mloc, __shfl_xor_sync(FM, mloc, o));
    float mx = fmaxf(mloc, 1e-8f);

    float4* optr = reinterpret_cast<float4*>(out + ((size_t)b * TFRAMES + t) * NPITCH);
    #pragma unroll
    for (int g = 0; g < 2; ++g) {
        float4 o4;
        o4.x = __fdividef(acc[g][0], mx);
        o4.y = __fdividef(acc[g][1], mx);
        o4.z = __fdividef(acc[g][2], mx);
        o4.w = __fdividef(acc[g][3], mx);
        optr[lane + 32 * g] = o4;
    }
}

extern "C" void kernel_launch(void* const* d_in, const int* in_sizes, int n_in,
                              void* d_out, int out_size)
{
    (void)in_sizes; (void)n_in; (void)out_size;
    const float* wav = (const float*)d_in[0];
    float* out = (float*)d_out;

    Params p;

    // Gather indices: f32 argmin over |linspace(0,12000,1025) - center_freq|
    const double l40 = log(40.0), l1000 = log(1000.0);
    for (int j = 0; j < NPITCH; ++j) {
        double cd = exp(l40 + (double)j * (l1000 - l40) / 255.0);
        float  cf = (float)cd;
        const float step = 11.71875f;
        int i0 = (int)(cd / 11.71875);
        int best = 0; float bestd = 3.4e38f;
        for (int i = i0 - 2; i <= i0 + 2; ++i) {
            int ic = i < 0 ? 0 : (i > 1024 ? 1024 : i);
            float d = fabsf((float)ic * step - cf);
            if (d < bestd) { bestd = d; best = ic; }
        }
        p.closest[j] = best;
    }

    // Harmonic shifts: Python round() == rint (half-even), identical expression
    const double cpb = 1200.0 * log2(25.0) / 255.0;
    p.shift[0] = 0; p.wgt[0] = 1.0f;
    for (int n = 2; n <= 8; ++n) {
        p.shift[n - 1] = (int)rint(1200.0 * log2((double)n) / cpb);
        p.wgt[n - 1]   = (float)pow(0.86, (double)(n - 1));
    }

    dim3 grid(TFRAMES, BATCH);
    pitch_kernel<<<grid, 32>>>(wav, out, p);
}

// round 16
// speedup vs baseline: 1.1248x; 1.1248x over previous
#include <cuda_runtime.h>
#include <math.h>
#include <stdint.h>

// Fixed problem shapes
#define HOP 256
#define NFFT 2048
#define NPITCH 256
#define BATCH 16
#define NSAMP 480000
#define TFRAMES 1876
#define KLA 102           // LA bins 0..101
#define LPAD 168          // zero-pad in front of LS (max shift 165)

struct Params {
    int   closest[NPITCH];
    int   shift[8];
    float wgt[8];
};

#define CR 0.7071067811865476f

// ---- f32x2 packed helpers (sm_100+; ptxas never auto-fuses these) ----
__device__ __forceinline__ unsigned long long F2U(float2 v) {
    return *reinterpret_cast<unsigned long long*>(&v);
}
__device__ __forceinline__ float2 U2F(unsigned long long u) {
    return *reinterpret_cast<float2*>(&u);
}
__device__ __forceinline__ float2 padd(float2 a, float2 b) {
    unsigned long long r;
    asm("add.rn.f32x2 %0, %1, %2;" : "=l"(r) : "l"(F2U(a)), "l"(F2U(b)));
    return U2F(r);
}
__device__ __forceinline__ float2 psub(float2 a, float2 b) {
    unsigned long long r;
    asm("sub.rn.f32x2 %0, %1, %2;" : "=l"(r) : "l"(F2U(a)), "l"(F2U(b)));
    return U2F(r);
}
__device__ __forceinline__ float2 pfma(float2 a, float2 b, float2 c) {
    unsigned long long r;
    asm("fma.rn.f32x2 %0, %1, %2, %3;" : "=l"(r) : "l"(F2U(a)), "l"(F2U(b)), "l"(F2U(c)));
    return U2F(r);
}

// radix-4 DIF butterfly on packed complex; add/sub packed, twiddle muls scalar
// (literal twiddles compile to FFMA-imm, rt=1). PM=(1,-1), MP=(-1,1) hoisted.
__device__ __forceinline__ void bfly4p(
    float2& a0, float2& a1, float2& a2, float2& a3,
    float c1, float s1, float c2, float s2, float c3, float s3,
    float2 PM, float2 MP)
{
    float2 t0 = padd(a0, a2), t1 = padd(a1, a3);
    float2 t2 = psub(a0, a2), t3 = psub(a1, a3);
    float2 y0 = padd(t0, t1), y2 = psub(t0, t1);
    float2 st3 = make_float2(t3.y, t3.x);
    float2 y1 = pfma(st3, PM, t2);   // (t2r+t3i, t2i-t3r)
    float2 y3 = pfma(st3, MP, t2);   // (t2r-t3i, t2i+t3r)
    a0 = y0;
    a1 = make_float2(y1.x * c1 - y1.y * s1, y1.x * s1 + y1.y * c1);
    a2 = make_float2(y2.x * c2 - y2.y * s2, y2.x * s2 + y2.y * c2);
    a3 = make_float2(y3.x * c3 - y3.y * s3, y3.x * s3 + y3.y * c3);
}

// In-register 32-pt DIF FFT (radix 4,4,2), packed complex. Output position p
// holds bin k = (p>>3) + 4*((p>>1)&3) + 16*(p&1). All twiddles literal.
__device__ __forceinline__ void fft32p(float2* z, float2 PM, float2 MP)
{
    constexpr float T32C[8] = { 1.0f, 0.98078528040323044913f, 0.92387953251128675613f,
        0.83146961230254523708f, 0.70710678118654752440f, 0.55557023301960222474f,
        0.38268343236508977173f, 0.19509032201612826785f };
    constexpr float T32S[8] = { 0.0f, -0.19509032201612826785f, -0.38268343236508977173f,
        -0.55557023301960222474f, -0.70710678118654752440f, -0.83146961230254523708f,
        -0.92387953251128675613f, -0.98078528040323044913f };
    constexpr float T16C[8] = { 1.0f, 0.92387953251128675613f, 0.70710678118654752440f,
        0.38268343236508977173f, 0.0f, -0.38268343236508977173f,
        -0.70710678118654752440f, -0.92387953251128675613f };
    constexpr float T16S[8] = { 0.0f, -0.38268343236508977173f, -0.70710678118654752440f,
        -0.92387953251128675613f, -1.0f, -0.92387953251128675613f,
        -0.70710678118654752440f, -0.38268343236508977173f };
    constexpr float T96C[8] = { 1.0f, 0.83146961230254523708f, 0.38268343236508977173f,
        -0.19509032201612826785f, -0.70710678118654752440f, -0.98078528040323044913f,
        -0.92387953251128675613f, -0.55557023301960222474f };
    constexpr float T96S[8] = { 0.0f, -0.55557023301960222474f, -0.92387953251128675613f,
        -0.98078528040323044913f, -0.70710678118654752440f, -0.19509032201612826785f,
        0.38268343236508977173f, 0.83146961230254523708f };

    #pragma unroll
    for (int q = 0; q < 8; ++q)
        bfly4p(z[q], z[q + 8], z[q + 16], z[q + 24],
               T32C[q], T32S[q], T16C[q], T16S[q], T96C[q], T96S[q], PM, MP);

    #pragma unroll
    for (int g = 0; g < 4; ++g) {
        const int bb = 8 * g;
        bfly4p(z[bb], z[bb + 2], z[bb + 4], z[bb + 6],
               1.f, 0.f, 1.f, 0.f, 1.f, 0.f, PM, MP);
        bfly4p(z[bb + 1], z[bb + 3], z[bb + 5], z[bb + 7],
               CR, -CR, 0.f, -1.f, -CR, -CR, PM, MP);
    }

    #pragma unroll
    for (int m = 0; m < 16; ++m) {
        float2 a = z[2 * m], bv = z[2 * m + 1];
        z[2 * m]     = padd(a, bv);
        z[2 * m + 1] = psub(a, bv);
    }
}

__global__ __launch_bounds__(32, 24)
void pitch_kernel(const float* __restrict__ wav, float* __restrict__ out, Params p)
{
    // TR: XOR-swizzled 32x32 float2 transpose buffer (exactly 1024 f2 = 8192 B).
    // After TR is consumed, SPX/LA/CS1/LSB alias the same storage.
    __shared__ __align__(16) float SH[2048];
    float2* TR  = reinterpret_cast<float2*>(SH);
    float2* SPX = reinterpret_cast<float2*>(SH);            // bins 0..102 (f2[0..103))
    float*  LA  = SH + 208;                                 // [208,312)
    float*  CS1 = SH + 312;                                 // [312,416)
    float*  LSB = SH + 416;                                 // [416,840)

    const int lane = threadIdx.x;     // 0..31
    const int t    = blockIdx.x;
    const int b    = blockIdx.y;
    const float* w = wav + (size_t)b * NSAMP;
    const int base = t * HOP - (NFFT / 2);
    const unsigned FM = 0xffffffffu;
    const float2 PM = make_float2(1.f, -1.f);
    const float2 MP = make_float2(-1.f, 1.f);

    // ---- load: thread n2=lane holds packed z[32*n1 + lane], n1 = 0..31 ----
    float2 z[32];
    if (base >= 0 && base + NFFT <= NSAMP) {
        const float2* src = reinterpret_cast<const float2*>(w + base);
        #pragma unroll
        for (int n1 = 0; n1 < 32; ++n1)
            z[n1] = src[32 * n1 + lane];
    } else {
        #pragma unroll
        for (int n1 = 0; n1 < 32; ++n1) {
            int m  = 32 * n1 + lane;
            int p0 = base + 2 * m, p1 = p0 + 1;
            p0 = p0 < 0 ? -p0 : (p0 >= NSAMP ? 2 * NSAMP - 2 - p0 : p0);
            p1 = p1 < 0 ? -p1 : (p1 >= NSAMP ? 2 * NSAMP - 2 - p1 : p1);
            z[n1] = make_float2(w[p0], w[p1]);
        }
    }

    // ---- step 1: full 32-pt FFT over n1 (packed) ----
    fft32p(z, PM, MP);

    // ---- twiddle W1024^{n2*k1} (batched powers, R14 form) + transpose-store ----
    {
        float bs, bc; __sincosf((float)lane * (-6.283185307179586f / 1024.0f), &bs, &bc);
        float b2c = bc * bc - bs * bs, b2s = 2.0f * bc * bs;
        float b3c = bc * b2c - bs * b2s, b3s = bc * b2s + bs * b2c;
        float b4c = b2c * b2c - b2s * b2s, b4s = 2.0f * b2c * b2s;
        float wc = 1.0f, ws = 0.0f;            // W^(4*j32*lane)
        #pragma unroll
        for (int j32 = 0; j32 < 8; ++j32) {
            #pragma unroll
            for (int j = 0; j < 4; ++j) {
                const int k1 = 4 * j32 + j;
                const int pp = 8 * (k1 & 3) + 2 * ((k1 >> 2) & 3) + (k1 >> 4);
                float twc, tws;
                if (j == 0)      { twc = wc; tws = ws; }
                else if (j == 1) { twc = wc * bc - ws * bs;   tws = wc * bs + ws * bc; }
                else if (j == 2) { twc = wc * b2c - ws * b2s; tws = wc * b2s + ws * b2c; }
                else             { twc = wc * b3c - ws * b3s; tws = wc * b3s + ws * b3c; }
                float2 v = z[pp];
                TR[32 * k1 + (lane ^ k1)] =
                    make_float2(v.x * twc - v.y * tws, v.x * tws + v.y * twc);
            }
            float nc = wc * b4c - ws * b4s, ns = wc * b4s + ws * b4c;
            wc = nc; ws = ns;
        }
    }
    __syncwarp();

    // ---- step 2: pruned streaming 32-pt DFT over n2 (thread = row k1 = lane).
    //      Needed k2 in {0,1,2,3,28,29,30,31}: Y[k2] = sum_j W32^{j*k2} V_j[k2&3],
    //      V_j built packed; accumulation scalar FFMA-imm (literal twiddles). ----
    float accR[8] = {0,0,0,0,0,0,0,0}, accI[8] = {0,0,0,0,0,0,0,0};
    {
        constexpr float C32[32] = {
            1.0f, 0.98078528040323044913f, 0.92387953251128675613f, 0.83146961230254523708f,
            0.70710678118654752440f, 0.55557023301960222474f, 0.38268343236508977173f,
            0.19509032201612826785f, 0.0f, -0.19509032201612826785f, -0.38268343236508977173f,
            -0.55557023301960222474f, -0.70710678118654752440f, -0.83146961230254523708f,
            -0.92387953251128675613f, -0.98078528040323044913f, -1.0f,
            -0.98078528040323044913f, -0.92387953251128675613f, -0.83146961230254523708f,
            -0.70710678118654752440f, -0.55557023301960222474f, -0.38268343236508977173f,
            -0.19509032201612826785f, 0.0f, 0.19509032201612826785f, 0.38268343236508977173f,
            0.55557023301960222474f, 0.70710678118654752440f, 0.83146961230254523708f,
            0.92387953251128675613f, 0.98078528040323044913f };
        constexpr float S32[32] = {
            0.0f, -0.19509032201612826785f, -0.38268343236508977173f, -0.55557023301960222474f,
            -0.70710678118654752440f, -0.83146961230254523708f, -0.92387953251128675613f,
            -0.98078528040323044913f, -1.0f, -0.98078528040323044913f,
            -0.92387953251128675613f, -0.83146961230254523708f, -0.70710678118654752440f,
            -0.55557023301960222474f, -0.38268343236508977173f, -0.19509032201612826785f,
            0.0f, 0.19509032201612826785f, 0.38268343236508977173f, 0.55557023301960222474f,
            0.70710678118654752440f, 0.83146961230254523708f, 0.92387953251128675613f,
            0.98078528040323044913f, 1.0f, 0.98078528040323044913f, 0.92387953251128675613f,
            0.83146961230254523708f, 0.70710678118654752440f, 0.55557023301960222474f,
            0.38268343236508977173f, 0.19509032201612826785f };
        constexpr int K2V[8] = {0, 1, 2, 3, 28, 29, 30, 31};

        #pragma unroll
        for (int j = 0; j < 8; ++j) {
            float2 a0 = TR[32 * lane + ((j     ) ^ lane)];
            float2 a1 = TR[32 * lane + ((j +  8) ^ lane)];
            float2 a2 = TR[32 * lane + ((j + 16) ^ lane)];
            float2 a3 = TR[32 * lane + ((j + 24) ^ lane)];
            float2 t0 = padd(a0, a2), t1 = padd(a1, a3);
            float2 t2 = psub(a0, a2), t3 = psub(a1, a3);
            float2 st3 = make_float2(t3.y, t3.x);
            float2 V[4];
            V[0] = padd(t0, t1);
            V[2] = psub(t0, t1);
            V[1] = pfma(st3, PM, t2);    // (t2r+t3i, t2i-t3r)
            V[3] = pfma(st3, MP, t2);    // (t2r-t3i, t2i+t3r)
            #pragma unroll
            for (int q = 0; q < 8; ++q) {
                const int k2 = K2V[q];
                const int r  = k2 & 3;
                const int tt = (k2 * j) & 31;
                accR[q] = fmaf(C32[tt], V[r].x, fmaf(-S32[tt], V[r].y, accR[q]));
                accI[q] = fmaf(C32[tt], V[r].y, fmaf( S32[tt], V[r].x, accI[q]));
            }
        }
    }
    __syncwarp();   // all TR reads done before SPX (aliased) writes

    // ---- rfft unpack in registers via shuffles -> SPX[0..102] ----
    // Thread lane holds bins lane+32q (q=0..3) and lane+896+32(q-4) (q=4..7).
    // Partner of bin k=lane+32q is bin 1024-k = (32-lane)&31 thread, acc[7-q]
    // (lane 0, q>=1: its own acc[8-q]; lane 0, q==0: conj self).
    {
        const int src = (32 - lane) & 31;
        #pragma unroll
        for (int q = 0; q < 4; ++q) {
            float br = __shfl_sync(FM, accR[7 - q], src);
            float bi = __shfl_sync(FM, accI[7 - q], src);
            if (lane == 0 && q > 0) { br = accR[8 - q]; bi = accI[8 - q]; }
            float Ar = accR[q], Ai = accI[q];
            float Br, Bi;
            if (q == 0 && lane == 0) { Br = Ar; Bi = Ai; }
            else                     { Br = br; Bi = bi; }
            int k = lane + 32 * q;
            float zer =  0.5f * (Ar + Br);
            float zei =  0.5f * (Ai - Bi);
            float zor =  0.5f * (Ai + Bi);
            float zoi = -0.5f * (Ar - Br);
            float sn, cs;
            __sincosf((float)k * (-3.141592653589793f / 1024.0f), &sn, &cs);
            if (q < 3 || lane <= 6)
                SPX[k] = make_float2(zer + cs * zor - sn * zoi,
                                     zei + cs * zoi + sn * zor);
        }
    }
    __syncwarp();

    // ---- window as spectral conv + log magnitude -> LA[0..101] ----
    #pragma unroll
    for (int it = 0; it < 4; ++it) {
        int k = lane + 32 * it;
        if (it < 3 || lane <= 5) {      // k < 102
            float2 Xc = SPX[k];
            float2 Xp = SPX[k + 1];
            float2 Xm = (k == 0) ? make_float2(SPX[1].x, -SPX[1].y) : SPX[k - 1];
            float xr = 0.5f * Xc.x - 0.25f * (Xm.x + Xp.x);
            float xi = 0.5f * Xc.y - 0.25f * (Xm.y + Xp.y);
            LA[k] = __logf(sqrtf(xr * xr + xi * xi) + 1e-8f);
        }
    }
    if (lane < 2) LA[KLA + lane] = 0.f;
    #pragma unroll
    for (int i = lane; i < LPAD / 4; i += 32)
        reinterpret_cast<float4*>(LSB)[i] = make_float4(0.f, 0.f, 0.f, 0.f);
    __syncwarp();

    // ---- single-pass warp scan: CS1 inclusive prefix of LA ----
    {
        float v0 = 0.f, v1 = 0.f, v2 = 0.f, v3 = 0.f;
        if (lane < 26) {
            float4 q = reinterpret_cast<const float4*>(LA)[lane];
            v0 = q.x; v1 = q.y; v2 = q.z; v3 = q.w;
        }
        float p1 = v0 + v1, p2 = p1 + v2, p3 = p2 + v3;
        float s = p3;
        #pragma unroll
        for (int o = 1; o < 32; o <<= 1) {
            float u = __shfl_up_sync(FM, s, o);
            if (lane >= o) s += u;
        }
        float excl = s - p3;
        if (lane < 26)
            reinterpret_cast<float4*>(CS1)[lane] =
                make_float4(excl + v0, excl + p1, excl + p2, excl + p3);
    }
    __syncwarp();

    // ---- fine structure: 8 pitch bins per thread (two float4 groups) ----
    float lsv[2][4];
    #pragma unroll
    for (int g = 0; g < 2; ++g) {
        int vt = lane + 32 * g;
        int4 c4 = reinterpret_cast<const int4*>(p.closest)[vt];
        int cis[4] = {c4.x, c4.y, c4.z, c4.w};
        float LA0 = LA[0];
        #pragma unroll
        for (int j = 0; j < 4; ++j) {
            int ci = cis[j];                  // 3..85
            int lo = ci - 15, hi = ci + 16;   // hi <= 101
            float sum = (lo <= 0) ? fmaf((float)(-lo), LA0, CS1[hi])
                                  : CS1[hi] - CS1[lo - 1];
            lsv[g][j] = __expf(LA[ci] - sum * 0.03125f);
        }
        *reinterpret_cast<float4*>(&LSB[LPAD + 4 * vt]) =
            make_float4(lsv[g][0], lsv[g][1], lsv[g][2], lsv[g][3]);
    }
    __syncwarp();

    // ---- subharmonic summation (zero-padded, guard-free) ----
    float acc[2][4];
    #pragma unroll
    for (int g = 0; g < 2; ++g)
        #pragma unroll
        for (int j = 0; j < 4; ++j) acc[g][j] = lsv[g][j];

    #pragma unroll
    for (int n = 1; n < 8; ++n) {
        int   sh = p.shift[n];
        float wn = p.wgt[n];
        #pragma unroll
        for (int g = 0; g < 2; ++g) {
            int bi = LPAD + 4 * (lane + 32 * g) - sh;     // >= 3 always
            if ((sh & 3) == 0) {
                float4 q = *reinterpret_cast<const float4*>(&LSB[bi]);
                acc[g][0] = fmaf(wn, q.x, acc[g][0]);
                acc[g][1] = fmaf(wn, q.y, acc[g][1]);
                acc[g][2] = fmaf(wn, q.z, acc[g][2]);
                acc[g][3] = fmaf(wn, q.w, acc[g][3]);
            } else if ((sh & 1) == 0) {
                float2 qa = *reinterpret_cast<const float2*>(&LSB[bi]);
                float2 qb = *reinterpret_cast<const float2*>(&LSB[bi + 2]);
                acc[g][0] = fmaf(wn, qa.x, acc[g][0]);
                acc[g][1] = fmaf(wn, qa.y, acc[g][1]);
                acc[g][2] = fmaf(wn, qb.x, acc[g][2]);
                acc[g][3] = fmaf(wn, qb.y, acc[g][3]);
            } else {
                #pragma unroll
                for (int j = 0; j < 4; ++j)
                    acc[g][j] = fmaf(wn, LSB[bi + j], acc[g][j]);
            }
        }
    }

    // ---- per-frame max (pure warp shuffle), normalize, store ----
    float mloc = -3.4e38f;
    #pragma unroll
    for (int g = 0; g < 2; ++g)
        #pragma unroll
        for (int j = 0; j < 4; ++j) mloc = fmaxf(mloc, acc[g][j]);
    #pragma unroll
    for (int o = 16; o; o >>= 1)
        mloc = fmaxf(mloc, __shfl_xor_sync(FM, mloc, o));
    float mx = fmaxf(mloc, 1e-8f);

    float4* optr = reinterpret_cast<float4*>(out + ((size_t)b * TFRAMES + t) * NPITCH);
    #pragma unroll
    for (int g = 0; g < 2; ++g) {
        float4 o4;
        o4.x = __fdividef(acc[g][0], mx);
        o4.y = __fdividef(acc[g][1], mx);
        o4.z = __fdividef(acc[g][2], mx);
        o4.w = __fdividef(acc[g][3], mx);
        optr[lane + 32 * g] = o4;
    }
}

extern "C" void kernel_launch(void* const* d_in, const int* in_sizes, int n_in,
                              void* d_out, int out_size)
{
    (void)in_sizes; (void)n_in; (void)out_size;
    const float* wav = (const float*)d_in[0];
    float* out = (float*)d_out;

    Params p;

    // Gather indices: f32 argmin over |linspace(0,12000,1025) - center_freq|
    const double l40 = log(40.0), l1000 = log(1000.0);
    for (int j = 0; j < NPITCH; ++j) {
        double cd = exp(l40 + (double)j * (l1000 - l40) / 255.0);
        float  cf = (float)cd;
        const float step = 11.71875f;
        int i0 = (int)(cd / 11.71875);
        int best = 0; float bestd = 3.4e38f;
        for (int i = i0 - 2; i <= i0 + 2; ++i) {
            int ic = i < 0 ? 0 : (i > 1024 ? 1024 : i);
            float d = fabsf((float)ic * step - cf);
            if (d < bestd) { bestd = d; best = ic; }
        }
        p.closest[j] = best;
    }

    // Harmonic shifts: Python round() == rint (half-even), identical expression
    const double cpb = 1200.0 * log2(25.0) / 255.0;
    p.shift[0] = 0; p.wgt[0] = 1.0f;
    for (int n = 2; n <= 8; ++n) {
        p.shift[n - 1] = (int)rint(1200.0 * log2((double)n) / cpb);
        p.wgt[n - 1]   = (float)pow(0.86, (double)(n - 1));
    }

    dim3 grid(TFRAMES, BATCH);
    pitch_kernel<<<grid, 32>>>(wav, out, p);
}

// round 17
// speedup vs baseline: 1.1364x; 1.0103x over previous
#include <cuda_runtime.h>
#include <math.h>
#include <stdint.h>

// Fixed problem shapes
#define HOP 256
#define NFFT 2048
#define NPITCH 256
#define BATCH 16
#define NSAMP 480000
#define TFRAMES 1876
#define KLA 102           // LA bins 0..101
#define LPAD 168          // zero-pad in front of LS (max shift 165)

struct Params {
    int   closest[NPITCH];
    int   shift[8];
    float wgt[8];
};

#define CR 0.7071067811865476f

// ---- f32x2 packed helpers (sm_100+; ptxas never auto-fuses these) ----
__device__ __forceinline__ unsigned long long F2U(float2 v) {
    return *reinterpret_cast<unsigned long long*>(&v);
}
__device__ __forceinline__ float2 U2F(unsigned long long u) {
    return *reinterpret_cast<float2*>(&u);
}
__device__ __forceinline__ float2 padd(float2 a, float2 b) {
    unsigned long long r;
    asm("add.rn.f32x2 %0, %1, %2;" : "=l"(r) : "l"(F2U(a)), "l"(F2U(b)));
    return U2F(r);
}
__device__ __forceinline__ float2 psub(float2 a, float2 b) {
    unsigned long long r;
    asm("sub.rn.f32x2 %0, %1, %2;" : "=l"(r) : "l"(F2U(a)), "l"(F2U(b)));
    return U2F(r);
}
__device__ __forceinline__ float2 pfma(float2 a, float2 b, float2 c) {
    unsigned long long r;
    asm("fma.rn.f32x2 %0, %1, %2, %3;" : "=l"(r) : "l"(F2U(a)), "l"(F2U(b)), "l"(F2U(c)));
    return U2F(r);
}

// radix-4 DIF butterfly on packed complex; add/sub packed, twiddle muls scalar
// (literal twiddles compile to FFMA-imm, rt=1). PM=(1,-1), MP=(-1,1) hoisted.
__device__ __forceinline__ void bfly4p(
    float2& a0, float2& a1, float2& a2, float2& a3,
    float c1, float s1, float c2, float s2, float c3, float s3,
    float2 PM, float2 MP)
{
    float2 t0 = padd(a0, a2), t1 = padd(a1, a3);
    float2 t2 = psub(a0, a2), t3 = psub(a1, a3);
    float2 y0 = padd(t0, t1), y2 = psub(t0, t1);
    float2 st3 = make_float2(t3.y, t3.x);
    float2 y1 = pfma(st3, PM, t2);   // (t2r+t3i, t2i-t3r)
    float2 y3 = pfma(st3, MP, t2);   // (t2r-t3i, t2i+t3r)
    a0 = y0;
    a1 = make_float2(y1.x * c1 - y1.y * s1, y1.x * s1 + y1.y * c1);
    a2 = make_float2(y2.x * c2 - y2.y * s2, y2.x * s2 + y2.y * c2);
    a3 = make_float2(y3.x * c3 - y3.y * s3, y3.x * s3 + y3.y * c3);
}

// In-register 32-pt DIF FFT (radix 4,4,2), packed complex. Output position p
// holds bin k = (p>>3) + 4*((p>>1)&3) + 16*(p&1). All twiddles literal.
__device__ __forceinline__ void fft32p(float2* z, float2 PM, float2 MP)
{
    constexpr float T32C[8] = { 1.0f, 0.98078528040323044913f, 0.92387953251128675613f,
        0.83146961230254523708f, 0.70710678118654752440f, 0.55557023301960222474f,
        0.38268343236508977173f, 0.19509032201612826785f };
    constexpr float T32S[8] = { 0.0f, -0.19509032201612826785f, -0.38268343236508977173f,
        -0.55557023301960222474f, -0.70710678118654752440f, -0.83146961230254523708f,
        -0.92387953251128675613f, -0.98078528040323044913f };
    constexpr float T16C[8] = { 1.0f, 0.92387953251128675613f, 0.70710678118654752440f,
        0.38268343236508977173f, 0.0f, -0.38268343236508977173f,
        -0.70710678118654752440f, -0.92387953251128675613f };
    constexpr float T16S[8] = { 0.0f, -0.38268343236508977173f, -0.70710678118654752440f,
        -0.92387953251128675613f, -1.0f, -0.92387953251128675613f,
        -0.70710678118654752440f, -0.38268343236508977173f };
    constexpr float T96C[8] = { 1.0f, 0.83146961230254523708f, 0.38268343236508977173f,
        -0.19509032201612826785f, -0.70710678118654752440f, -0.98078528040323044913f,
        -0.92387953251128675613f, -0.55557023301960222474f };
    constexpr float T96S[8] = { 0.0f, -0.55557023301960222474f, -0.92387953251128675613f,
        -0.98078528040323044913f, -0.70710678118654752440f, -0.19509032201612826785f,
        0.38268343236508977173f, 0.83146961230254523708f };

    #pragma unroll
    for (int q = 0; q < 8; ++q)
        bfly4p(z[q], z[q + 8], z[q + 16], z[q + 24],
               T32C[q], T32S[q], T16C[q], T16S[q], T96C[q], T96S[q], PM, MP);

    #pragma unroll
    for (int g = 0; g < 4; ++g) {
        const int bb = 8 * g;
        bfly4p(z[bb], z[bb + 2], z[bb + 4], z[bb + 6],
               1.f, 0.f, 1.f, 0.f, 1.f, 0.f, PM, MP);
        bfly4p(z[bb + 1], z[bb + 3], z[bb + 5], z[bb + 7],
               CR, -CR, 0.f, -1.f, -CR, -CR, PM, MP);
    }

    #pragma unroll
    for (int m = 0; m < 16; ++m) {
        float2 a = z[2 * m], bv = z[2 * m + 1];
        z[2 * m]     = padd(a, bv);
        z[2 * m + 1] = psub(a, bv);
    }
}

__global__ __launch_bounds__(32, 24)
void pitch_kernel(const float* __restrict__ wav, float* __restrict__ out, Params p)
{
    // TR: column-major transpose buffer. Element (k1, n2) at word 68*n2 + 2*k1
    //   -> float2 index 34*n2 + k1, float4 (k1-pair) index 17*n2 + m.
    // Writer (fixed n2=lane): 16 STS.128, conflict-free (8-lane phases tile all
    // 32 banks). Reader (fixed k1=lane): 32 LDS.64 stride 34 f2, conflict-free.
    // After TR is consumed, SPX/LA/CS1/LSB alias the same storage.
    __shared__ __align__(16) float SH[2176];
    float2* TR2 = reinterpret_cast<float2*>(SH);
    float4* TF4 = reinterpret_cast<float4*>(SH);
    float2* SPX = reinterpret_cast<float2*>(SH);            // bins 0..102 (f2[0..103))
    float*  LA  = SH + 208;                                 // [208,312)
    float*  CS1 = SH + 312;                                 // [312,416)
    float*  LSB = SH + 416;                                 // [416,840)

    const int lane = threadIdx.x;     // 0..31
    const int t    = blockIdx.x;
    const int b    = blockIdx.y;
    const float* w = wav + (size_t)b * NSAMP;
    const int base = t * HOP - (NFFT / 2);
    const unsigned FM = 0xffffffffu;
    const float2 PM = make_float2(1.f, -1.f);
    const float2 MP = make_float2(-1.f, 1.f);

    // ---- load: thread n2=lane holds packed z[32*n1 + lane], n1 = 0..31 ----
    float2 z[32];
    if (base >= 0 && base + NFFT <= NSAMP) {
        const float2* src = reinterpret_cast<const float2*>(w + base);
        #pragma unroll
        for (int n1 = 0; n1 < 32; ++n1)
            z[n1] = src[32 * n1 + lane];
    } else {
        #pragma unroll
        for (int n1 = 0; n1 < 32; ++n1) {
            int m  = 32 * n1 + lane;
            int p0 = base + 2 * m, p1 = p0 + 1;
            p0 = p0 < 0 ? -p0 : (p0 >= NSAMP ? 2 * NSAMP - 2 - p0 : p0);
            p1 = p1 < 0 ? -p1 : (p1 >= NSAMP ? 2 * NSAMP - 2 - p1 : p1);
            z[n1] = make_float2(w[p0], w[p1]);
        }
    }

    // ---- step 1: full 32-pt FFT over n1 (packed) ----
    fft32p(z, PM, MP);

    // ---- twiddle W1024^{n2*k1} (batched powers) + STS.128 transpose-store ----
    // k1 = 4*j32 + j: sources are z[pp], z[pp+8], z[pp+16], z[pp+24],
    // pp = 2*(j32&3) + (j32>>2). Two float4 per j32 (k1-pairs).
    {
        float bs, bc; __sincosf((float)lane * (-6.283185307179586f / 1024.0f), &bs, &bc);
        float b2c = bc * bc - bs * bs, b2s = 2.0f * bc * bs;
        float b3c = bc * b2c - bs * b2s, b3s = bc * b2s + bs * b2c;
        float b4c = b2c * b2c - b2s * b2s, b4s = 2.0f * b2c * b2s;
        float wc = 1.0f, ws = 0.0f;            // W^(4*j32*lane)
        #pragma unroll
        for (int j32 = 0; j32 < 8; ++j32) {
            const int pp = 2 * (j32 & 3) + (j32 >> 2);
            float t1c = wc * bc  - ws * bs,  t1s = wc * bs  + ws * bc;
            float t2c = wc * b2c - ws * b2s, t2s = wc * b2s + ws * b2c;
            float t3c = wc * b3c - ws * b3s, t3s = wc * b3s + ws * b3c;
            float2 va = z[pp], vb = z[pp + 8], vc = z[pp + 16], vd = z[pp + 24];
            float4 P0, P1;
            P0.x = va.x * wc  - va.y * ws;  P0.y = va.x * ws  + va.y * wc;
            P0.z = vb.x * t1c - vb.y * t1s; P0.w = vb.x * t1s + vb.y * t1c;
            P1.x = vc.x * t2c - vc.y * t2s; P1.y = vc.x * t2s + vc.y * t2c;
            P1.z = vd.x * t3c - vd.y * t3s; P1.w = vd.x * t3s + vd.y * t3c;
            TF4[17 * lane + 2 * j32]     = P0;
            TF4[17 * lane + 2 * j32 + 1] = P1;
            float nc = wc * b4c - ws * b4s, ns = wc * b4s + ws * b4c;
            wc = nc; ws = ns;
        }
    }
    __syncwarp();

    // ---- step 2: pruned streaming 32-pt DFT over n2 (thread = row k1 = lane).
    //      Needed k2 in {0,1,2,3,28,29,30,31}: Y[k2] = sum_j W32^{j*k2} V_j[k2&3],
    //      V_j built packed; accumulation scalar FFMA-imm (literal twiddles). ----
    float accR[8] = {0,0,0,0,0,0,0,0}, accI[8] = {0,0,0,0,0,0,0,0};
    {
        constexpr float C32[32] = {
            1.0f, 0.98078528040323044913f, 0.92387953251128675613f, 0.83146961230254523708f,
            0.70710678118654752440f, 0.55557023301960222474f, 0.38268343236508977173f,
            0.19509032201612826785f, 0.0f, -0.19509032201612826785f, -0.38268343236508977173f,
            -0.55557023301960222474f, -0.70710678118654752440f, -0.83146961230254523708f,
            -0.92387953251128675613f, -0.98078528040323044913f, -1.0f,
            -0.98078528040323044913f, -0.92387953251128675613f, -0.83146961230254523708f,
            -0.70710678118654752440f, -0.55557023301960222474f, -0.38268343236508977173f,
            -0.19509032201612826785f, 0.0f, 0.19509032201612826785f, 0.38268343236508977173f,
            0.55557023301960222474f, 0.70710678118654752440f, 0.83146961230254523708f,
            0.92387953251128675613f, 0.98078528040323044913f };
        constexpr float S32[32] = {
            0.0f, -0.19509032201612826785f, -0.38268343236508977173f, -0.55557023301960222474f,
            -0.70710678118654752440f, -0.83146961230254523708f, -0.92387953251128675613f,
            -0.98078528040323044913f, -1.0f, -0.98078528040323044913f,
            -0.92387953251128675613f, -0.83146961230254523708f, -0.70710678118654752440f,
            -0.55557023301960222474f, -0.38268343236508977173f, -0.19509032201612826785f,
            0.0f, 0.19509032201612826785f, 0.38268343236508977173f, 0.55557023301960222474f,
            0.70710678118654752440f, 0.83146961230254523708f, 0.92387953251128675613f,
            0.98078528040323044913f, 1.0f, 0.98078528040323044913f, 0.92387953251128675613f,
            0.83146961230254523708f, 0.70710678118654752440f, 0.55557023301960222474f,
            0.38268343236508977173f, 0.19509032201612826785f };
        constexpr int K2V[8] = {0, 1, 2, 3, 28, 29, 30, 31};

        #pragma unroll
        for (int j = 0; j < 8; ++j) {
            float2 a0 = TR2[34 * (j     ) + lane];
            float2 a1 = TR2[34 * (j +  8) + lane];
            float2 a2 = TR2[34 * (j + 16) + lane];
            float2 a3 = TR2[34 * (j + 24) + lane];
            float2 t0 = padd(a0, a2), t1 = padd(a1, a3);
            float2 t2 = psub(a0, a2), t3 = psub(a1, a3);
            float2 st3 = make_float2(t3.y, t3.x);
            float2 V[4];
            V[0] = padd(t0, t1);
            V[2] = psub(t0, t1);
            V[1] = pfma(st3, PM, t2);    // (t2r+t3i, t2i-t3r)
            V[3] = pfma(st3, MP, t2);    // (t2r-t3i, t2i+t3r)
            #pragma unroll
            for (int q = 0; q < 8; ++q) {
                const int k2 = K2V[q];
                const int r  = k2 & 3;
                const int tt = (k2 * j) & 31;
                accR[q] = fmaf(C32[tt], V[r].x, fmaf(-S32[tt], V[r].y, accR[q]));
                accI[q] = fmaf(C32[tt], V[r].y, fmaf( S32[tt], V[r].x, accI[q]));
            }
        }
    }
    __syncwarp();   // all TR reads done before SPX (aliased) writes

    // ---- rfft unpack in registers via shuffles -> SPX[0..102] ----
    // Thread lane holds bins lane+32q (q=0..3) and lane+896+32(q-4) (q=4..7).
    // Partner of bin k=lane+32q is bin 1024-k = (32-lane)&31 thread, acc[7-q]
    // (lane 0, q>=1: its own acc[8-q]; lane 0, q==0: conj self).
    {
        const int src = (32 - lane) & 31;
        #pragma unroll
        for (int q = 0; q < 4; ++q) {
            float br = __shfl_sync(FM, accR[7 - q], src);
            float bi = __shfl_sync(FM, accI[7 - q], src);
            if (lane == 0 && q > 0) { br = accR[8 - q]; bi = accI[8 - q]; }
            float Ar = accR[q], Ai = accI[q];
            float Br, Bi;
            if (q == 0 && lane == 0) { Br = Ar; Bi = Ai; }
            else                     { Br = br; Bi = bi; }
            int k = lane + 32 * q;
            float zer =  0.5f * (Ar + Br);
            float zei =  0.5f * (Ai - Bi);
            float zor =  0.5f * (Ai + Bi);
            float zoi = -0.5f * (Ar - Br);
            float sn, cs;
            __sincosf((float)k * (-3.141592653589793f / 1024.0f), &sn, &cs);
            if (q < 3 || lane <= 6)
                SPX[k] = make_float2(zer + cs * zor - sn * zoi,
                                     zei + cs * zoi + sn * zor);
        }
    }
    __syncwarp();

    // ---- window as spectral conv + log magnitude -> LA[0..101] ----
    #pragma unroll
    for (int it = 0; it < 4; ++it) {
        int k = lane + 32 * it;
        if (it < 3 || lane <= 5) {      // k < 102
            float2 Xc = SPX[k];
            float2 Xp = SPX[k + 1];
            float2 Xm = (k == 0) ? make_float2(SPX[1].x, -SPX[1].y) : SPX[k - 1];
            float xr = 0.5f * Xc.x - 0.25f * (Xm.x + Xp.x);
            float xi = 0.5f * Xc.y - 0.25f * (Xm.y + Xp.y);
            LA[k] = __logf(sqrtf(xr * xr + xi * xi) + 1e-8f);
        }
    }
    if (lane < 2) LA[KLA + lane] = 0.f;
    #pragma unroll
    for (int i = lane; i < LPAD / 4; i += 32)
        reinterpret_cast<float4*>(LSB)[i] = make_float4(0.f, 0.f, 0.f, 0.f);
    __syncwarp();

    // ---- single-pass warp scan: CS1 inclusive prefix of LA ----
    {
        float v0 = 0.f, v1 = 0.f, v2 = 0.f, v3 = 0.f;
        if (lane < 26) {
            float4 q = reinterpret_cast<const float4*>(LA)[lane];
            v0 = q.x; v1 = q.y; v2 = q.z; v3 = q.w;
        }
        float p1 = v0 + v1, p2 = p1 + v2, p3 = p2 + v3;
        float s = p3;
        #pragma unroll
        for (int o = 1; o < 32; o <<= 1) {
            float u = __shfl_up_sync(FM, s, o);
            if (lane >= o) s += u;
        }
        float excl = s - p3;
        if (lane < 26)
            reinterpret_cast<float4*>(CS1)[lane] =
                make_float4(excl + v0, excl + p1, excl + p2, excl + p3);
    }
    __syncwarp();

    // ---- fine structure: 8 pitch bins per thread (two float4 groups) ----
    float lsv[2][4];
    #pragma unroll
    for (int g = 0; g < 2; ++g) {
        int vt = lane + 32 * g;
        int4 c4 = reinterpret_cast<const int4*>(p.closest)[vt];
        int cis[4] = {c4.x, c4.y, c4.z, c4.w};
        float LA0 = LA[0];
        #pragma unroll
        for (int j = 0; j < 4; ++j) {
            int ci = cis[j];                  // 3..85
            int lo = ci - 15, hi = ci + 16;   // hi <= 101
            float sum = (lo <= 0) ? fmaf((float)(-lo), LA0, CS1[hi])
                                  : CS1[hi] - CS1[lo - 1];
            lsv[g][j] = __expf(LA[ci] - sum * 0.03125f);
        }
        *reinterpret_cast<float4*>(&LSB[LPAD + 4 * vt]) =
            make_float4(lsv[g][0], lsv[g][1], lsv[g][2], lsv[g][3]);
    }
    __syncwarp();

    // ---- subharmonic summation (zero-padded, guard-free) ----
    float acc[2][4];
    #pragma unroll
    for (int g = 0; g < 2; ++g)
        #pragma unroll
        for (int j = 0; j < 4; ++j) acc[g][j] = lsv[g][j];

    #pragma unroll
    for (int n = 1; n < 8; ++n) {
        int   sh = p.shift[n];
        float wn = p.wgt[n];
        #pragma unroll
        for (int g = 0; g < 2; ++g) {
            int bi = LPAD + 4 * (lane + 32 * g) - sh;     // >= 3 always
            if ((sh & 3) == 0) {
                float4 q = *reinterpret_cast<const float4*>(&LSB[bi]);
                acc[g][0] = fmaf(wn, q.x, acc[g][0]);
                acc[g][1] = fmaf(wn, q.y, acc[g][1]);
                acc[g][2] = fmaf(wn, q.z, acc[g][2]);
                acc[g][3] = fmaf(wn, q.w, acc[g][3]);
            } else if ((sh & 1) == 0) {
                float2 qa = *reinterpret_cast<const float2*>(&LSB[bi]);
                float2 qb = *reinterpret_cast<const float2*>(&LSB[bi + 2]);
                acc[g][0] = fmaf(wn, qa.x, acc[g][0]);
                acc[g][1] = fmaf(wn, qa.y, acc[g][1]);
                acc[g][2] = fmaf(wn, qb.x, acc[g][2]);
                acc[g][3] = fmaf(wn, qb.y, acc[g][3]);
            } else {
                #pragma unroll
                for (int j = 0; j < 4; ++j)
                    acc[g][j] = fmaf(wn, LSB[bi + j], acc[g][j]);
            }
        }
    }

    // ---- per-frame max (pure warp shuffle), normalize, store ----
    float mloc = -3.4e38f;
    #pragma unroll
    for (int g = 0; g < 2; ++g)
        #pragma unroll
        for (int j = 0; j < 4; ++j) mloc = fmaxf(mloc, acc[g][j]);
    #pragma unroll
    for (int o = 16; o; o >>= 1)
        mloc = fmaxf(mloc, __shfl_xor_sync(FM, mloc, o));
    float mx = fmaxf(mloc, 1e-8f);

    float4* optr = reinterpret_cast<float4*>(out + ((size_t)b * TFRAMES + t) * NPITCH);
    #pragma unroll
    for (int g = 0; g < 2; ++g) {
        float4 o4;
        o4.x = __fdividef(acc[g][0], mx);
        o4.y = __fdividef(acc[g][1], mx);
        o4.z = __fdividef(acc[g][2], mx);
        o4.w = __fdividef(acc[g][3], mx);
        optr[lane + 32 * g] = o4;
    }
}

extern "C" void kernel_launch(void* const* d_in, const int* in_sizes, int n_in,
                              void* d_out, int out_size)
{
    (void)in_sizes; (void)n_in; (void)out_size;
    const float* wav = (const float*)d_in[0];
    float* out = (float*)d_out;

    Params p;

    // Gather indices: f32 argmin over |linspace(0,12000,1025) - center_freq|
    const double l40 = log(40.0), l1000 = log(1000.0);
    for (int j = 0; j < NPITCH; ++j) {
        double cd = exp(l40 + (double)j * (l1000 - l40) / 255.0);
        float  cf = (float)cd;
        const float step = 11.71875f;
        int i0 = (int)(cd / 11.71875);
        int best = 0; float bestd = 3.4e38f;
        for (int i = i0 - 2; i <= i0 + 2; ++i) {
            int ic = i < 0 ? 0 : (i > 1024 ? 1024 : i);
            float d = fabsf((float)ic * step - cf);
            if (d < bestd) { bestd = d; best = ic; }
        }
        p.closest[j] = best;
    }

    // Harmonic shifts: Python round() == rint (half-even), identical expression
    const double cpb = 1200.0 * log2(25.0) / 255.0;
    p.shift[0] = 0; p.wgt[0] = 1.0f;
    for (int n = 2; n <= 8; ++n) {
        p.shift[n - 1] = (int)rint(1200.0 * log2((double)n) / cpb);
        p.wgt[n - 1]   = (float)pow(0.86, (double)(n - 1));
    }

    dim3 grid(TFRAMES, BATCH);
    pitch_kernel<<<grid, 32>>>(wav, out, p);
}